// round 5
// baseline (speedup 1.0000x reference)
#include <cuda_runtime.h>
#include <cuda_bf16.h>
#include <stdint.h>

// ---------------------------------------------------------------------------
// KMaxPool: per row of 4096 fp32, top-8 values in original index order.
// One warp per row, single pass.
//   - 32 elems/lane/iter; bf16-truncated packed max filter:
//       PRMT packs high-16 bits of fp32 pairs (exact bf16 truncation, alu pipe)
//       __hmax2 bf16x2 tree (fma-pipe datapath) -> chunk max in trunc space
//     Conservative: tr monotone => v > vmin implies tr(v) >= tr(vmin).
//   - qualifying chunks rescanned with exact fp32/64-bit keyed insertion
//   - ballot-gated warp threshold refresh
//   - exact 64-bit bitonic warp merge at the end
// ---------------------------------------------------------------------------

static __device__ __forceinline__ uint32_t bmax2(uint32_t a, uint32_t b) {
    __nv_bfloat162 av = *reinterpret_cast<__nv_bfloat162*>(&a);
    __nv_bfloat162 bv = *reinterpret_cast<__nv_bfloat162*>(&b);
    __nv_bfloat162 r  = __hmax2(av, bv);
    return *reinterpret_cast<uint32_t*>(&r);
}

static __device__ __forceinline__ unsigned long long fkey(float v, uint32_t idx) {
    uint32_t b = __float_as_uint(v);
    uint32_t u = (b & 0x80000000u) ? ~b : (b | 0x80000000u);
    return ((unsigned long long)u << 32) | (uint32_t)(~idx);
}

static __device__ __forceinline__ float kval(unsigned long long k) {
    uint32_t u = (uint32_t)(k >> 32);
    uint32_t b = (u & 0x80000000u) ? (u ^ 0x80000000u) : ~u;
    return __uint_as_float(b);
}

// Sentinel: -inf with worst tie-break index; kval(SENTINEL_KEY) == -inf.
#define SENTINEL_KEY 0x007FFFFF00000000ull

#define CSWAP_DESC(a, b)                                     \
    do {                                                     \
        if ((a) < (b)) {                                     \
            unsigned long long _t = (a); (a) = (b); (b) = _t;\
        }                                                    \
    } while (0)

__global__ void __launch_bounds__(256) kmax8_kernel(const float* __restrict__ x,
                                                    float* __restrict__ out,
                                                    int nrows) {
    const int gw   = (int)((blockIdx.x * blockDim.x + threadIdx.x) >> 5);
    const int lane = threadIdx.x & 31;
    if (gw >= nrows) return;

    const uint4* row = reinterpret_cast<const uint4*>(x) + (size_t)gw * 1024;

    unsigned long long t[8];
#pragma unroll
    for (int i = 0; i < 8; ++i) t[i] = SENTINEL_KEY;
    float vmin = __int_as_float(0xff800000);   // exact reject threshold (-inf)
    float trf  = __int_as_float(0xff800000);   // bf16-truncated threshold

    // Exact 64-bit keyed insert (rare path).
    auto consider = [&](uint32_t bits, uint32_t idx) {
        float v = __uint_as_float(bits);
        if (v > vmin) {
            t[7] = fkey(v, idx);
#pragma unroll
            for (int j = 7; j > 0; --j) {
                if (t[j] > t[j - 1]) {
                    unsigned long long tmp = t[j]; t[j] = t[j - 1]; t[j - 1] = tmp;
                }
            }
            vmin = fmaxf(vmin, kval(t[7]));
        }
    };

    // 4 iterations x 32 elements/lane = 128 elements/lane = 4096/row.
#pragma unroll 1
    for (int it = 0; it < 4; ++it) {
        const int base = it * 256;  // float4-granularity position
        uint4 vv[8];
#pragma unroll
        for (int j = 0; j < 8; ++j) vv[j] = row[base + j * 32 + lane];

        // Pack bf16 truncations: high 16 bits of each fp32. 2 elems per PRMT.
        uint32_t b[16];
#pragma unroll
        for (int j = 0; j < 8; ++j) {
            b[2 * j]     = __byte_perm(vv[j].x, vv[j].y, 0x7632);
            b[2 * j + 1] = __byte_perm(vv[j].z, vv[j].w, 0x7632);
        }

        // Packed bf16x2 max tree: 15 HMNMX2 (fma-pipe datapath).
        uint32_t m01 = bmax2(bmax2(bmax2(b[0], b[1]), bmax2(b[2], b[3])),
                             bmax2(bmax2(b[4], b[5]), bmax2(b[6], b[7])));
        uint32_t m23 = bmax2(bmax2(bmax2(b[8], b[9]), bmax2(b[10], b[11])),
                             bmax2(bmax2(b[12], b[13]), bmax2(b[14], b[15])));
        uint32_t mm = bmax2(m01, m23);

        // Unpack both bf16 lanes to exact fp32 (bit ops only).
        float flo  = __uint_as_float(mm << 16);
        float fhi  = __uint_as_float(mm & 0xffff0000u);
        float cmax = fmaxf(flo, fhi);

        // Conservative filter in truncated space.
        bool q = (cmax >= trf);
        if (q) {
            // exact rescan in ascending index order
#pragma unroll
            for (int j = 0; j < 8; ++j) {
                uint32_t eb = (uint32_t)(base + j * 32 + lane) * 4u;
                consider(vv[j].x, eb + 0);
                consider(vv[j].y, eb + 1);
                consider(vv[j].z, eb + 2);
                consider(vv[j].w, eb + 3);
            }
        }

        // Ballot-gated warp threshold refresh (skipped when nothing changed).
        if (__ballot_sync(0xffffffffu, q)) {
            float my8 = kval(t[7]);
#pragma unroll
            for (int m = 16; m >= 1; m >>= 1)
                my8 = fmaxf(my8, __shfl_xor_sync(0xffffffffu, my8, m));
            vmin = fmaxf(vmin, my8);
            trf  = __uint_as_float(__float_as_uint(vmin) & 0xffff0000u);
        }
    }

    // Exact warp butterfly merge: 5 rounds (reverse-max merge + bitonic clean).
#pragma unroll
    for (int m = 16; m >= 1; m >>= 1) {
        unsigned long long c[8];
#pragma unroll
        for (int i = 0; i < 8; ++i) {
            unsigned long long bb = __shfl_xor_sync(0xffffffffu, t[7 - i], m);
            c[i] = (t[i] > bb) ? t[i] : bb;
        }
        CSWAP_DESC(c[0], c[4]); CSWAP_DESC(c[1], c[5]);
        CSWAP_DESC(c[2], c[6]); CSWAP_DESC(c[3], c[7]);
        CSWAP_DESC(c[0], c[2]); CSWAP_DESC(c[1], c[3]);
        CSWAP_DESC(c[4], c[6]); CSWAP_DESC(c[5], c[7]);
        CSWAP_DESC(c[0], c[1]); CSWAP_DESC(c[2], c[3]);
        CSWAP_DESC(c[4], c[5]); CSWAP_DESC(c[6], c[7]);
#pragma unroll
        for (int i = 0; i < 8; ++i) t[i] = c[i];
    }

    // Reorder global top-8 by ascending original index (= descending ~idx).
#pragma unroll
    for (int i = 0; i < 7; ++i) {
#pragma unroll
        for (int j = 0; j < 7 - i; ++j) {
            if ((uint32_t)t[j] < (uint32_t)t[j + 1]) {
                unsigned long long tmp = t[j]; t[j] = t[j + 1]; t[j + 1] = tmp;
            }
        }
    }

    if (lane == 0) {
        float* o = out + (size_t)gw * 8;
#pragma unroll
        for (int i = 0; i < 8; ++i) o[i] = kval(t[i]);
    }
}

extern "C" void kernel_launch(void* const* d_in, const int* in_sizes, int n_in,
                              void* d_out, int out_size) {
    const float* x = (const float*)d_in[0];
    float* out = (float*)d_out;
    int nrows = in_sizes[0] / 4096;
    const int threads = 256;
    const int warps_per_block = threads / 32;
    int blocks = (nrows + warps_per_block - 1) / warps_per_block;
    kmax8_kernel<<<blocks, threads>>>(x, out, nrows);
}

// round 6
// speedup vs baseline: 4.9831x; 4.9831x over previous
#include <cuda_runtime.h>
#include <stdint.h>

// ---------------------------------------------------------------------------
// KMaxPool: per row of 4096 fp32, top-8 values in original index order.
// One warp per row, single pass. Warp-cooperative selection:
//   - warp top-8 kept DISTRIBUTED in lanes 0..7 (val desc), vmin = lane7 val
//   - per element: setp + ballot + uniform branch (no divergent rescans)
//   - qualifying events handled by a uniform ballot loop; each insert is a
//     one-slot-per-lane shfl_up shift of the distributed list
//   - threshold tightens after every insert -> ~57 events per warp expected
//   - epilogue: rank lanes 0..7 by original index, scatter-store 8 floats
// Ties in value produce identical output bytes regardless of index winner.
// ---------------------------------------------------------------------------

#define FULLMASK 0xffffffffu

// Process one element position: all 32 lanes present their element v (own
// element index = ubase + 4*lane). Updates the distributed top-8 and vmin.
static __device__ __forceinline__ void proc(float v, uint32_t ubase,
                                            float& val, uint32_t& idx,
                                            float& vmin, bool lane0) {
    unsigned m = __ballot_sync(FULLMASK, v > vmin);
    while (m) {
        const int L = __ffs(m) - 1;
        m &= m - 1;
        const float    bv = __shfl_sync(FULLMASK, v, L);
        const uint32_t bi = ubase + ((uint32_t)L << 2);

        // distributed insert: shift list down by one from the insert point
        const float    pv = __shfl_up_sync(FULLMASK, val, 1);
        const uint32_t pi = __shfl_up_sync(FULLMASK, idx, 1);
        const bool keep = (val >= bv);            // incumbent wins ties
        const bool pk   = lane0 || (pv >= bv);    // lane0: conceptual prev=+inf
        val = keep ? val : (pk ? bv : pv);
        idx = keep ? idx : (pk ? bi : pi);

        vmin = __shfl_sync(FULLMASK, val, 7);
        if (!m) break;
        m &= __ballot_sync(FULLMASK, v > vmin);   // prune with tighter vmin
    }
}

__global__ void __launch_bounds__(256) kmax8_kernel(const float* __restrict__ x,
                                                    float* __restrict__ out,
                                                    int nrows) {
    const int gw   = (int)((blockIdx.x * blockDim.x + threadIdx.x) >> 5);
    const int lane = threadIdx.x & 31;
    if (gw >= nrows) return;

    const uint4* row = reinterpret_cast<const uint4*>(x) + (size_t)gw * 1024;

    float    val  = __int_as_float(0xff800000);  // -inf (lanes 0..7 = top-8)
    uint32_t idx  = 0;
    float    vmin = __int_as_float(0xff800000);
    const bool lane0 = (lane == 0);

    // 8 batches x 4 float4-loads x 4 components = 128 elements per lane.
#pragma unroll 1
    for (int it = 0; it < 8; ++it) {
        const int p0 = it * 128 + lane;          // float4 position of load a
        uint4 a = row[p0];
        uint4 b = row[p0 + 32];
        uint4 c = row[p0 + 64];
        uint4 d = row[p0 + 96];
        // uniform element-index bases (lane contribution added inside proc)
        const uint32_t u0 = (uint32_t)(it * 512);
        const uint32_t u1 = u0 + 128;
        const uint32_t u2 = u0 + 256;
        const uint32_t u3 = u0 + 384;

        proc(__uint_as_float(a.x), u0 + 0, val, idx, vmin, lane0);
        proc(__uint_as_float(a.y), u0 + 1, val, idx, vmin, lane0);
        proc(__uint_as_float(a.z), u0 + 2, val, idx, vmin, lane0);
        proc(__uint_as_float(a.w), u0 + 3, val, idx, vmin, lane0);

        proc(__uint_as_float(b.x), u1 + 0, val, idx, vmin, lane0);
        proc(__uint_as_float(b.y), u1 + 1, val, idx, vmin, lane0);
        proc(__uint_as_float(b.z), u1 + 2, val, idx, vmin, lane0);
        proc(__uint_as_float(b.w), u1 + 3, val, idx, vmin, lane0);

        proc(__uint_as_float(c.x), u2 + 0, val, idx, vmin, lane0);
        proc(__uint_as_float(c.y), u2 + 1, val, idx, vmin, lane0);
        proc(__uint_as_float(c.z), u2 + 2, val, idx, vmin, lane0);
        proc(__uint_as_float(c.w), u2 + 3, val, idx, vmin, lane0);

        proc(__uint_as_float(d.x), u3 + 0, val, idx, vmin, lane0);
        proc(__uint_as_float(d.y), u3 + 1, val, idx, vmin, lane0);
        proc(__uint_as_float(d.z), u3 + 2, val, idx, vmin, lane0);
        proc(__uint_as_float(d.w), u3 + 3, val, idx, vmin, lane0);
    }

    // Epilogue: lanes 0..7 hold the top-8 (val desc, unique idx).
    // rank = number of held indices smaller than mine -> output position.
    int rank = 0;
#pragma unroll
    for (int dd = 1; dd < 8; ++dd) {
        uint32_t oi = __shfl_sync(FULLMASK, idx, (lane + dd) & 7);
        rank += (oi < idx) ? 1 : 0;
    }
    if (lane < 8) out[(size_t)gw * 8 + rank] = val;
}

extern "C" void kernel_launch(void* const* d_in, const int* in_sizes, int n_in,
                              void* d_out, int out_size) {
    const float* x = (const float*)d_in[0];
    float* out = (float*)d_out;
    int nrows = in_sizes[0] / 4096;
    const int threads = 256;
    const int warps_per_block = threads / 32;
    int blocks = (nrows + warps_per_block - 1) / warps_per_block;
    kmax8_kernel<<<blocks, threads>>>(x, out, nrows);
}